// round 1
// baseline (speedup 1.0000x reference)
#include <cuda_runtime.h>
#include <cuda_bf16.h>
#include <math.h>

#define BB  4
#define NBB 262144
#define NAA 8192
#define NF  32

// output layout: bonds_out | atoms_out | state_out
#define O_ATOMS (BB * NBB * NF)              // 33554432
#define O_STATE (O_ATOMS + BB * NAA * NF)    // 34603008

// ---------------- scratch (device globals; zeroed each launch) --------------
__device__ float g_atom_acc[BB * NAA * NF];   // scatter sums
__device__ float g_counts[BB * NAA];          // scatter counts
__device__ float g_bond_sum[BB * NF];         // per-batch bond feature sums
__device__ float g_atom_sum[BB * NF];         // per-batch atom feature sums

__device__ __forceinline__ float sp(float x) {
    // softplus = max(x,0) + log1p(exp(-|x|))  (matches jax logaddexp(x,0))
    float ax = fabsf(x);
    return fmaxf(x, 0.0f) + log1pf(__expf(-ax));
}

// ---------------- zero scratch ---------------------------------------------
__global__ void k_zero() {
    int i = blockIdx.x * blockDim.x + threadIdx.x;
    int stride = gridDim.x * blockDim.x;
    for (int e = i; e < BB * NAA * NF; e += stride) g_atom_acc[e] = 0.0f;
    for (int e = i; e < BB * NAA; e += stride)      g_counts[e]   = 0.0f;
    if (i < BB * NF) { g_bond_sum[i] = 0.0f; g_atom_sum[i] = 0.0f; }
}

// ---------------- bond MLP (the big one) ------------------------------------
// 128 bonds per block; e_in = [a1(32) | a2(32) | bond(32)] staged in smem,
// state folded into layer-1 bias.
// smem floats: Xs 128*97 | w1 96*64 | w2 64*64 | w3 64*32 | be1 64 | be2 64 |
//              be3 32 | ia1 128(int) | ia2 128(int)  => 25120 floats = 100480 B
__global__ void __launch_bounds__(128)
k_bonds(const float* __restrict__ bonds,
        const int*   __restrict__ ba1,
        const int*   __restrict__ ba2,
        const float* __restrict__ atoms,
        const float* __restrict__ state,
        const float* __restrict__ w1, const float* __restrict__ b1,
        const float* __restrict__ w2, const float* __restrict__ b2,
        const float* __restrict__ w3, const float* __restrict__ b3,
        float* __restrict__ out)
{
    extern __shared__ float sm[];
    float* Xs  = sm;                 // 128 * 97
    float* w1s = Xs  + 128 * 97;     // 6144
    float* w2s = w1s + 6144;         // 4096
    float* w3s = w2s + 4096;         // 2048
    float* be1 = w3s + 2048;         // 64
    float* be2 = be1 + 64;           // 64
    float* be3 = be2 + 64;           // 32
    int*   ia1 = (int*)(be3 + 32);   // 128
    int*   ia2 = ia1 + 128;          // 128

    const int t    = threadIdx.x;
    const int b    = blockIdx.x >> 11;          // 2048 tiles / batch
    const int row0 = (blockIdx.x & 2047) << 7;  // * 128

    // indices
    ia1[t] = ba1[b * NBB + row0 + t];
    ia2[t] = ba2[b * NBB + row0 + t];

    // bond features (contiguous): cols 64..95
    {
        const float* src = bonds + ((size_t)b * NBB + row0) * NF;
        for (int e = t; e < 128 * NF; e += 128) {
            int r = e >> 5, c = e & 31;
            Xs[r * 97 + 64 + c] = src[e];
        }
    }
    // weights
    for (int e = t; e < 96 * 64; e += 128) w1s[e] = w1[e];
    for (int e = t; e < 64 * 64; e += 128) w2s[e] = w2[e];
    for (int e = t; e < 64 * 32; e += 128) w3s[e] = w3[e];
    // fold state into layer-1 bias
    if (t < 64) {
        float s = b1[t];
        #pragma unroll
        for (int i = 0; i < 32; i++) s += state[b * 32 + i] * w1[(96 + i) * 64 + t];
        be1[t] = s;
        be2[t] = b2[t];
    }
    if (t < 32) be3[t] = b3[t];

    __syncthreads();  // ia ready

    // gather a1 (cols 0..31) and a2 (cols 32..63): 8 threads per row, float4
    {
        int g = t >> 3, l4 = (t & 7) * 4;
        #pragma unroll
        for (int p = 0; p < 8; p++) {
            int r = p * 16 + g;
            const float4 v1 = *(const float4*)(atoms + ((size_t)b * NAA + ia1[r]) * NF + l4);
            Xs[r * 97 + l4 + 0] = v1.x; Xs[r * 97 + l4 + 1] = v1.y;
            Xs[r * 97 + l4 + 2] = v1.z; Xs[r * 97 + l4 + 3] = v1.w;
            const float4 v2 = *(const float4*)(atoms + ((size_t)b * NAA + ia2[r]) * NF + l4);
            Xs[r * 97 + 32 + l4 + 0] = v2.x; Xs[r * 97 + 32 + l4 + 1] = v2.y;
            Xs[r * 97 + 32 + l4 + 2] = v2.z; Xs[r * 97 + 32 + l4 + 3] = v2.w;
        }
    }
    __syncthreads();

    const int ro = t * 97;
    float acc[64];

    // ---- layer 1: 96 -> 64 ----
    #pragma unroll
    for (int j = 0; j < 64; j++) acc[j] = be1[j];
    for (int i = 0; i < 96; i++) {
        float xv = Xs[ro + i];
        const float4* wr = (const float4*)(w1s + i * 64);
        #pragma unroll
        for (int q = 0; q < 16; q++) {
            float4 w = wr[q];
            acc[4 * q + 0] += xv * w.x; acc[4 * q + 1] += xv * w.y;
            acc[4 * q + 2] += xv * w.z; acc[4 * q + 3] += xv * w.w;
        }
    }
    #pragma unroll
    for (int j = 0; j < 64; j++) Xs[ro + j] = sp(acc[j]);

    // ---- layer 2: 64 -> 64 ----
    #pragma unroll
    for (int j = 0; j < 64; j++) acc[j] = be2[j];
    for (int i = 0; i < 64; i++) {
        float xv = Xs[ro + i];
        const float4* wr = (const float4*)(w2s + i * 64);
        #pragma unroll
        for (int q = 0; q < 16; q++) {
            float4 w = wr[q];
            acc[4 * q + 0] += xv * w.x; acc[4 * q + 1] += xv * w.y;
            acc[4 * q + 2] += xv * w.z; acc[4 * q + 3] += xv * w.w;
        }
    }
    #pragma unroll
    for (int j = 0; j < 64; j++) Xs[ro + j] = sp(acc[j]);

    // ---- layer 3: 64 -> 32 ----
    #pragma unroll
    for (int j = 0; j < 32; j++) acc[j] = be3[j];
    for (int i = 0; i < 64; i++) {
        float xv = Xs[ro + i];
        const float4* wr = (const float4*)(w3s + i * 32);
        #pragma unroll
        for (int q = 0; q < 8; q++) {
            float4 w = wr[q];
            acc[4 * q + 0] += xv * w.x; acc[4 * q + 1] += xv * w.y;
            acc[4 * q + 2] += xv * w.z; acc[4 * q + 3] += xv * w.w;
        }
    }
    #pragma unroll
    for (int j = 0; j < 32; j++) acc[j] = sp(acc[j]);

    // scatter-add into atoms accumulator + counts
    {
        int a = ia1[t];
        float* ap = g_atom_acc + ((size_t)b * NAA + a) * NF;
        #pragma unroll
        for (int c = 0; c < 32; c++) atomicAdd(ap + c, acc[c]);
        atomicAdd(&g_counts[b * NAA + a], 1.0f);
    }

    // stage outputs -> smem for coalesced write + column sums
    #pragma unroll
    for (int c = 0; c < 32; c++) Xs[ro + c] = acc[c];
    __syncthreads();

    if (t < 32) {
        float s = 0.0f;
        for (int r = 0; r < 128; r++) s += Xs[r * 97 + t];
        atomicAdd(&g_bond_sum[b * NF + t], s);
    }
    {
        float* op = out + ((size_t)b * NBB + row0) * NF;
        for (int e = t; e < 128 * NF; e += 128)
            op[e] = Xs[(e >> 5) * 97 + (e & 31)];
    }
}

// ---------------- atom MLP ---------------------------------------------------
// v_in = [bonds_to_atoms(32) | atoms(32)], state folded into bias.
// smem floats: Xs 128*65 | w1 64*64 | w2 64*64 | w3 64*32 | be1 64 | be2 64 |
//              be3 32 | cnt 128  => 18848 floats = 75392 B
__global__ void __launch_bounds__(128)
k_atoms(const float* __restrict__ atoms,
        const float* __restrict__ state,
        const float* __restrict__ w1, const float* __restrict__ b1,
        const float* __restrict__ w2, const float* __restrict__ b2,
        const float* __restrict__ w3, const float* __restrict__ b3,
        float* __restrict__ out)
{
    extern __shared__ float sm[];
    float* Xs  = sm;                 // 128*65
    float* w1s = Xs  + 128 * 65;     // 4096
    float* w2s = w1s + 4096;         // 4096
    float* w3s = w2s + 4096;         // 2048
    float* be1 = w3s + 2048;         // 64
    float* be2 = be1 + 64;           // 64
    float* be3 = be2 + 64;           // 32
    float* cnt = be3 + 32;           // 128

    const int t    = threadIdx.x;
    const int b    = blockIdx.x >> 6;          // 64 tiles / batch
    const int row0 = (blockIdx.x & 63) << 7;

    cnt[t] = g_counts[b * NAA + row0 + t];

    // atoms features: cols 32..63
    {
        const float* src = atoms + ((size_t)b * NAA + row0) * NF;
        for (int e = t; e < 128 * NF; e += 128) {
            int r = e >> 5, c = e & 31;
            Xs[r * 65 + 32 + c] = src[e];
        }
    }
    for (int e = t; e < 64 * 64; e += 128) w1s[e] = w1[e];
    for (int e = t; e < 64 * 64; e += 128) w2s[e] = w2[e];
    for (int e = t; e < 64 * 32; e += 128) w3s[e] = w3[e];
    if (t < 64) {
        float s = b1[t];
        #pragma unroll
        for (int i = 0; i < 32; i++) s += state[b * 32 + i] * w1[(64 + i) * 64 + t];
        be1[t] = s;
        be2[t] = b2[t];
    }
    if (t < 32) be3[t] = b3[t];
    __syncthreads();  // cnt ready

    // bonds_to_atoms = acc / count: cols 0..31
    {
        const float* src = g_atom_acc + ((size_t)b * NAA + row0) * NF;
        for (int e = t; e < 128 * NF; e += 128) {
            int r = e >> 5, c = e & 31;
            float cv = cnt[r];
            Xs[r * 65 + c] = (cv > 0.0f) ? src[e] / cv : 0.0f;
        }
    }
    __syncthreads();

    const int ro = t * 65;
    float acc[64];

    #pragma unroll
    for (int j = 0; j < 64; j++) acc[j] = be1[j];
    for (int i = 0; i < 64; i++) {
        float xv = Xs[ro + i];
        const float4* wr = (const float4*)(w1s + i * 64);
        #pragma unroll
        for (int q = 0; q < 16; q++) {
            float4 w = wr[q];
            acc[4 * q + 0] += xv * w.x; acc[4 * q + 1] += xv * w.y;
            acc[4 * q + 2] += xv * w.z; acc[4 * q + 3] += xv * w.w;
        }
    }
    #pragma unroll
    for (int j = 0; j < 64; j++) Xs[ro + j] = sp(acc[j]);

    #pragma unroll
    for (int j = 0; j < 64; j++) acc[j] = be2[j];
    for (int i = 0; i < 64; i++) {
        float xv = Xs[ro + i];
        const float4* wr = (const float4*)(w2s + i * 64);
        #pragma unroll
        for (int q = 0; q < 16; q++) {
            float4 w = wr[q];
            acc[4 * q + 0] += xv * w.x; acc[4 * q + 1] += xv * w.y;
            acc[4 * q + 2] += xv * w.z; acc[4 * q + 3] += xv * w.w;
        }
    }
    #pragma unroll
    for (int j = 0; j < 64; j++) Xs[ro + j] = sp(acc[j]);

    #pragma unroll
    for (int j = 0; j < 32; j++) acc[j] = be3[j];
    for (int i = 0; i < 64; i++) {
        float xv = Xs[ro + i];
        const float4* wr = (const float4*)(w3s + i * 32);
        #pragma unroll
        for (int q = 0; q < 8; q++) {
            float4 w = wr[q];
            acc[4 * q + 0] += xv * w.x; acc[4 * q + 1] += xv * w.y;
            acc[4 * q + 2] += xv * w.z; acc[4 * q + 3] += xv * w.w;
        }
    }
    #pragma unroll
    for (int j = 0; j < 32; j++) acc[j] = sp(acc[j]);

    #pragma unroll
    for (int c = 0; c < 32; c++) Xs[ro + c] = acc[c];
    __syncthreads();

    if (t < 32) {
        float s = 0.0f;
        for (int r = 0; r < 128; r++) s += Xs[r * 65 + t];
        atomicAdd(&g_atom_sum[b * NF + t], s);
    }
    {
        float* op = out + O_ATOMS + ((size_t)b * NAA + row0) * NF;
        for (int e = t; e < 128 * NF; e += 128)
            op[e] = Xs[(e >> 5) * 65 + (e & 31)];
    }
}

// ---------------- state MLP --------------------------------------------------
__global__ void __launch_bounds__(256)
k_state(const float* __restrict__ state,
        const float* __restrict__ w1, const float* __restrict__ b1,
        const float* __restrict__ w2, const float* __restrict__ b2,
        const float* __restrict__ w3, const float* __restrict__ b3,
        float* __restrict__ out)
{
    __shared__ float uin[BB][96];
    __shared__ float hh[BB][64];
    const int t = threadIdx.x;

    if (t < BB * 32) {
        int b = t >> 5, i = t & 31;
        uin[b][i]      = g_bond_sum[b * 32 + i] * (1.0f / NBB);
        uin[b][32 + i] = g_atom_sum[b * 32 + i] * (1.0f / NAA);
        uin[b][64 + i] = state[b * 32 + i];
    }
    __syncthreads();

    const int b = t >> 6, j = t & 63;
    float s = b1[j];
    for (int i = 0; i < 96; i++) s += uin[b][i] * w1[i * 64 + j];
    hh[b][j] = sp(s);
    __syncthreads();

    s = b2[j];
    for (int i = 0; i < 64; i++) s += hh[b][i] * w2[i * 64 + j];
    float h2v = sp(s);
    __syncthreads();
    hh[b][j] = h2v;
    __syncthreads();

    if (j < 32) {
        s = b3[j];
        for (int i = 0; i < 64; i++) s += hh[b][i] * w3[i * 32 + j];
        out[O_STATE + b * 32 + j] = sp(s);
    }
}

// ---------------- launch -----------------------------------------------------
extern "C" void kernel_launch(void* const* d_in, const int* in_sizes, int n_in,
                              void* d_out, int out_size)
{
    const float* bonds  = (const float*)d_in[0];
    const int*   ba1    = (const int*)  d_in[1];
    const int*   ba2    = (const int*)  d_in[2];
    const float* atoms  = (const float*)d_in[3];
    const float* state  = (const float*)d_in[4];
    const float* e_w1 = (const float*)d_in[5],  *e_b1 = (const float*)d_in[6];
    const float* e_w2 = (const float*)d_in[7],  *e_b2 = (const float*)d_in[8];
    const float* e_w3 = (const float*)d_in[9],  *e_b3 = (const float*)d_in[10];
    const float* v_w1 = (const float*)d_in[11], *v_b1 = (const float*)d_in[12];
    const float* v_w2 = (const float*)d_in[13], *v_b2 = (const float*)d_in[14];
    const float* v_w3 = (const float*)d_in[15], *v_b3 = (const float*)d_in[16];
    const float* u_w1 = (const float*)d_in[17], *u_b1 = (const float*)d_in[18];
    const float* u_w2 = (const float*)d_in[19], *u_b2 = (const float*)d_in[20];
    const float* u_w3 = (const float*)d_in[21], *u_b3 = (const float*)d_in[22];
    float* out = (float*)d_out;

    const int SMEM_BONDS = 25120 * 4;  // 100480 B
    const int SMEM_ATOMS = 18848 * 4;  //  75392 B
    cudaFuncSetAttribute(k_bonds, cudaFuncAttributeMaxDynamicSharedMemorySize, SMEM_BONDS);
    cudaFuncSetAttribute(k_atoms, cudaFuncAttributeMaxDynamicSharedMemorySize, SMEM_ATOMS);

    k_zero<<<512, 256>>>();
    k_bonds<<<BB * (NBB / 128), 128, SMEM_BONDS>>>(
        bonds, ba1, ba2, atoms, state,
        e_w1, e_b1, e_w2, e_b2, e_w3, e_b3, out);
    k_atoms<<<BB * (NAA / 128), 128, SMEM_ATOMS>>>(
        atoms, state,
        v_w1, v_b1, v_w2, v_b2, v_w3, v_b3, out);
    k_state<<<1, 256>>>(state, u_w1, u_b1, u_w2, u_b2, u_w3, u_b3, out);
}

// round 2
// speedup vs baseline: 1.2769x; 1.2769x over previous
#include <cuda_runtime.h>
#include <cuda_bf16.h>
#include <math.h>

#define BB  4
#define NBB 262144
#define NAA 8192
#define NF  32

// output layout: bonds_out | atoms_out | state_out
#define O_ATOMS (BB * NBB * NF)              // 33554432
#define O_STATE (O_ATOMS + BB * NAA * NF)    // 34603008

// ---------------- scratch (device globals; zeroed each launch) --------------
__device__ float g_atom_acc[BB * NAA * NF];   // scatter sums
__device__ float g_counts[BB * NAA];          // scatter counts
__device__ float g_bond_sum[BB * NF];         // per-batch bond feature sums
__device__ float g_atom_sum[BB * NF];         // per-batch atom feature sums

// ---------------- helpers ----------------------------------------------------
__device__ __forceinline__ float sp(float x) {
    // softplus = max(x,0) + log(1 + exp(-|x|)); fast MUFU path (err << 1e-3 budget)
    float ax = fabsf(x);
    return fmaxf(x, 0.0f) + __logf(1.0f + __expf(-ax));
}

__device__ __forceinline__ unsigned long long pack2(float a, float b) {
    unsigned long long r;
    asm("mov.b64 %0, {%1, %2};" : "=l"(r) : "f"(a), "f"(b));
    return r;
}
__device__ __forceinline__ float2 unpack2(unsigned long long v) {
    float2 r;
    asm("mov.b64 {%0, %1}, %2;" : "=f"(r.x), "=f"(r.y) : "l"(v));
    return r;
}
// packed dual fp32 FMA: d = a*b + d  (FFMA2)
__device__ __forceinline__ void ffma2(unsigned long long& d,
                                      unsigned long long a,
                                      unsigned long long b) {
    asm("fma.rn.f32x2 %0, %1, %2, %0;" : "+l"(d) : "l"(a), "l"(b));
}

// ---------------- zero scratch ---------------------------------------------
__global__ void k_zero() {
    int i = blockIdx.x * blockDim.x + threadIdx.x;
    int stride = gridDim.x * blockDim.x;
    for (int e = i; e < BB * NAA * NF; e += stride) g_atom_acc[e] = 0.0f;
    for (int e = i; e < BB * NAA; e += stride)      g_counts[e]   = 0.0f;
    if (i < BB * NF) { g_bond_sum[i] = 0.0f; g_atom_sum[i] = 0.0f; }
}

// ---------------- bond MLP (the big one) ------------------------------------
// 128 bonds/block, 256 threads: 2 threads per row, each owns 32 of 64 cols
// (16 of 32 in layer 3). e_in = [a1(32)|a2(32)|bond(32)] in smem; state folded
// into layer-1 bias. FFMA2 packed math throughout.
// smem floats: Xs 128*97 | w1 96*64 | w2 64*64 | w3 64*32 | be1 64 | be2 64 |
//              be3 32 | ia1 128(int) | ia2 128(int)  => 25120 floats = 100480 B
__global__ void __launch_bounds__(256)
k_bonds(const float* __restrict__ bonds,
        const int*   __restrict__ ba1,
        const int*   __restrict__ ba2,
        const float* __restrict__ atoms,
        const float* __restrict__ state,
        const float* __restrict__ w1, const float* __restrict__ b1,
        const float* __restrict__ w2, const float* __restrict__ b2,
        const float* __restrict__ w3, const float* __restrict__ b3,
        float* __restrict__ out)
{
    extern __shared__ float sm[];
    float* Xs  = sm;                 // 128 * 97
    float* w1s = Xs  + 128 * 97;     // 6144
    float* w2s = w1s + 6144;         // 4096
    float* w3s = w2s + 4096;         // 2048
    float* be1 = w3s + 2048;         // 64
    float* be2 = be1 + 64;           // 64
    float* be3 = be2 + 64;           // 32
    int*   ia1 = (int*)(be3 + 32);   // 128
    int*   ia2 = ia1 + 128;          // 128

    const int t    = threadIdx.x;
    const int row  = t & 127;
    const int half = t >> 7;                    // 0 or 1
    const int b    = blockIdx.x >> 11;          // 2048 tiles / batch
    const int row0 = (blockIdx.x & 2047) << 7;  // * 128

    // indices
    if (t < 128) {
        ia1[t] = ba1[b * NBB + row0 + t];
        ia2[t] = ba2[b * NBB + row0 + t];
    }

    // bond features (contiguous): cols 64..95
    {
        const float* src = bonds + ((size_t)b * NBB + row0) * NF;
        for (int e = t; e < 128 * NF; e += 256) {
            int r = e >> 5, c = e & 31;
            Xs[r * 97 + 64 + c] = src[e];
        }
    }
    // weights
    for (int e = t; e < 96 * 64; e += 256) w1s[e] = w1[e];
    for (int e = t; e < 64 * 64; e += 256) w2s[e] = w2[e];
    for (int e = t; e < 64 * 32; e += 256) w3s[e] = w3[e];
    // fold state into layer-1 bias
    if (t < 64) {
        float s = b1[t];
        #pragma unroll
        for (int i = 0; i < 32; i++) s += state[b * 32 + i] * w1[(96 + i) * 64 + t];
        be1[t] = s;
        be2[t] = b2[t];
    }
    if (t >= 64 && t < 96) be3[t - 64] = b3[t - 64];

    __syncthreads();  // ia ready

    // gather a1 (cols 0..31) and a2 (cols 32..63): 8 threads per row, float4
    {
        int g = t >> 3, l4 = (t & 7) * 4;   // g: 0..31
        #pragma unroll
        for (int p = 0; p < 4; p++) {
            int r = p * 32 + g;
            const float4 v1 = *(const float4*)(atoms + ((size_t)b * NAA + ia1[r]) * NF + l4);
            Xs[r * 97 + l4 + 0] = v1.x; Xs[r * 97 + l4 + 1] = v1.y;
            Xs[r * 97 + l4 + 2] = v1.z; Xs[r * 97 + l4 + 3] = v1.w;
            const float4 v2 = *(const float4*)(atoms + ((size_t)b * NAA + ia2[r]) * NF + l4);
            Xs[r * 97 + 32 + l4 + 0] = v2.x; Xs[r * 97 + 32 + l4 + 1] = v2.y;
            Xs[r * 97 + 32 + l4 + 2] = v2.z; Xs[r * 97 + 32 + l4 + 3] = v2.w;
        }
    }
    __syncthreads();

    const int ro = row * 97;
    const int co = half << 5;   // col offset for L1/L2 (0 or 32)
    unsigned long long acc[16];

    // ---- layer 1: 96 -> 64 (this thread: 32 cols) ----
    #pragma unroll
    for (int q = 0; q < 16; q++) acc[q] = pack2(be1[co + 2*q], be1[co + 2*q + 1]);
    for (int i = 0; i < 96; i++) {
        float xv = Xs[ro + i];
        unsigned long long xv2 = pack2(xv, xv);
        const ulonglong2* wr = (const ulonglong2*)(w1s + i * 64 + co);
        #pragma unroll
        for (int q = 0; q < 8; q++) {
            ulonglong2 w = wr[q];
            ffma2(acc[2*q + 0], xv2, w.x);
            ffma2(acc[2*q + 1], xv2, w.y);
        }
    }
    __syncthreads();   // all reads of Xs done before writes
    #pragma unroll
    for (int q = 0; q < 16; q++) {
        float2 v = unpack2(acc[q]);
        Xs[ro + co + 2*q]     = sp(v.x);
        Xs[ro + co + 2*q + 1] = sp(v.y);
    }
    __syncthreads();

    // ---- layer 2: 64 -> 64 ----
    #pragma unroll
    for (int q = 0; q < 16; q++) acc[q] = pack2(be2[co + 2*q], be2[co + 2*q + 1]);
    for (int i = 0; i < 64; i++) {
        float xv = Xs[ro + i];
        unsigned long long xv2 = pack2(xv, xv);
        const ulonglong2* wr = (const ulonglong2*)(w2s + i * 64 + co);
        #pragma unroll
        for (int q = 0; q < 8; q++) {
            ulonglong2 w = wr[q];
            ffma2(acc[2*q + 0], xv2, w.x);
            ffma2(acc[2*q + 1], xv2, w.y);
        }
    }
    __syncthreads();
    #pragma unroll
    for (int q = 0; q < 16; q++) {
        float2 v = unpack2(acc[q]);
        Xs[ro + co + 2*q]     = sp(v.x);
        Xs[ro + co + 2*q + 1] = sp(v.y);
    }
    __syncthreads();

    // ---- layer 3: 64 -> 32 (this thread: 16 cols) ----
    const int co3 = half << 4;  // 0 or 16
    #pragma unroll
    for (int q = 0; q < 8; q++) acc[q] = pack2(be3[co3 + 2*q], be3[co3 + 2*q + 1]);
    for (int i = 0; i < 64; i++) {
        float xv = Xs[ro + i];
        unsigned long long xv2 = pack2(xv, xv);
        const ulonglong2* wr = (const ulonglong2*)(w3s + i * 32 + co3);
        #pragma unroll
        for (int q = 0; q < 4; q++) {
            ulonglong2 w = wr[q];
            ffma2(acc[2*q + 0], xv2, w.x);
            ffma2(acc[2*q + 1], xv2, w.y);
        }
    }
    float o[16];
    #pragma unroll
    for (int q = 0; q < 8; q++) {
        float2 v = unpack2(acc[q]);
        o[2*q]     = sp(v.x);
        o[2*q + 1] = sp(v.y);
    }

    // scatter-add into atoms accumulator + counts
    {
        int a = ia1[row];
        float* ap = g_atom_acc + ((size_t)b * NAA + a) * NF + co3;
        #pragma unroll
        for (int c = 0; c < 16; c++) atomicAdd(ap + c, o[c]);
        if (half == 0) atomicAdd(&g_counts[b * NAA + a], 1.0f);
    }

    // stage outputs -> smem for coalesced write + column sums
    __syncthreads();   // reads of Xs (layer-3 inputs) done before overwrite
    #pragma unroll
    for (int c = 0; c < 16; c++) Xs[ro + co3 + c] = o[c];
    __syncthreads();

    if (t < 32) {
        float s = 0.0f;
        for (int r = 0; r < 128; r++) s += Xs[r * 97 + t];
        atomicAdd(&g_bond_sum[b * NF + t], s);
    }
    {
        float* op = out + ((size_t)b * NBB + row0) * NF;
        for (int e = t; e < 128 * NF; e += 256)
            op[e] = Xs[(e >> 5) * 97 + (e & 31)];
    }
}

// ---------------- atom MLP ---------------------------------------------------
// v_in = [bonds_to_atoms(32) | atoms(32)], state folded into bias.
// 256 threads, same split scheme.
// smem floats: Xs 128*65 | w1 64*64 | w2 64*64 | w3 64*32 | be1 64 | be2 64 |
//              be3 32 | cnt 128  => 18848 floats = 75392 B
__global__ void __launch_bounds__(256)
k_atoms(const float* __restrict__ atoms,
        const float* __restrict__ state,
        const float* __restrict__ w1, const float* __restrict__ b1,
        const float* __restrict__ w2, const float* __restrict__ b2,
        const float* __restrict__ w3, const float* __restrict__ b3,
        float* __restrict__ out)
{
    extern __shared__ float sm[];
    float* Xs  = sm;                 // 128*65
    float* w1s = Xs  + 128 * 65;     // 4096
    float* w2s = w1s + 4096;         // 4096
    float* w3s = w2s + 4096;         // 2048
    float* be1 = w3s + 2048;         // 64
    float* be2 = be1 + 64;           // 64
    float* be3 = be2 + 64;           // 32
    float* cnt = be3 + 32;           // 128

    const int t    = threadIdx.x;
    const int row  = t & 127;
    const int half = t >> 7;
    const int b    = blockIdx.x >> 6;          // 64 tiles / batch
    const int row0 = (blockIdx.x & 63) << 7;

    if (t < 128) cnt[t] = g_counts[b * NAA + row0 + t];

    // atoms features: cols 32..63
    {
        const float* src = atoms + ((size_t)b * NAA + row0) * NF;
        for (int e = t; e < 128 * NF; e += 256) {
            int r = e >> 5, c = e & 31;
            Xs[r * 65 + 32 + c] = src[e];
        }
    }
    for (int e = t; e < 64 * 64; e += 256) w1s[e] = w1[e];
    for (int e = t; e < 64 * 64; e += 256) w2s[e] = w2[e];
    for (int e = t; e < 64 * 32; e += 256) w3s[e] = w3[e];
    if (t < 64) {
        float s = b1[t];
        #pragma unroll
        for (int i = 0; i < 32; i++) s += state[b * 32 + i] * w1[(64 + i) * 64 + t];
        be1[t] = s;
        be2[t] = b2[t];
    }
    if (t >= 64 && t < 96) be3[t - 64] = b3[t - 64];
    __syncthreads();  // cnt ready

    // bonds_to_atoms = acc / count: cols 0..31
    {
        const float* src = g_atom_acc + ((size_t)b * NAA + row0) * NF;
        for (int e = t; e < 128 * NF; e += 256) {
            int r = e >> 5, c = e & 31;
            float cv = cnt[r];
            Xs[r * 65 + c] = (cv > 0.0f) ? src[e] / cv : 0.0f;
        }
    }
    __syncthreads();

    const int ro = row * 65;
    const int co = half << 5;
    unsigned long long acc[16];

    // ---- layer 1: 64 -> 64 ----
    #pragma unroll
    for (int q = 0; q < 16; q++) acc[q] = pack2(be1[co + 2*q], be1[co + 2*q + 1]);
    for (int i = 0; i < 64; i++) {
        float xv = Xs[ro + i];
        unsigned long long xv2 = pack2(xv, xv);
        const ulonglong2* wr = (const ulonglong2*)(w1s + i * 64 + co);
        #pragma unroll
        for (int q = 0; q < 8; q++) {
            ulonglong2 w = wr[q];
            ffma2(acc[2*q + 0], xv2, w.x);
            ffma2(acc[2*q + 1], xv2, w.y);
        }
    }
    __syncthreads();
    #pragma unroll
    for (int q = 0; q < 16; q++) {
        float2 v = unpack2(acc[q]);
        Xs[ro + co + 2*q]     = sp(v.x);
        Xs[ro + co + 2*q + 1] = sp(v.y);
    }
    __syncthreads();

    // ---- layer 2: 64 -> 64 ----
    #pragma unroll
    for (int q = 0; q < 16; q++) acc[q] = pack2(be2[co + 2*q], be2[co + 2*q + 1]);
    for (int i = 0; i < 64; i++) {
        float xv = Xs[ro + i];
        unsigned long long xv2 = pack2(xv, xv);
        const ulonglong2* wr = (const ulonglong2*)(w2s + i * 64 + co);
        #pragma unroll
        for (int q = 0; q < 8; q++) {
            ulonglong2 w = wr[q];
            ffma2(acc[2*q + 0], xv2, w.x);
            ffma2(acc[2*q + 1], xv2, w.y);
        }
    }
    __syncthreads();
    #pragma unroll
    for (int q = 0; q < 16; q++) {
        float2 v = unpack2(acc[q]);
        Xs[ro + co + 2*q]     = sp(v.x);
        Xs[ro + co + 2*q + 1] = sp(v.y);
    }
    __syncthreads();

    // ---- layer 3: 64 -> 32 ----
    const int co3 = half << 4;
    #pragma unroll
    for (int q = 0; q < 8; q++) acc[q] = pack2(be3[co3 + 2*q], be3[co3 + 2*q + 1]);
    for (int i = 0; i < 64; i++) {
        float xv = Xs[ro + i];
        unsigned long long xv2 = pack2(xv, xv);
        const ulonglong2* wr = (const ulonglong2*)(w3s + i * 32 + co3);
        #pragma unroll
        for (int q = 0; q < 4; q++) {
            ulonglong2 w = wr[q];
            ffma2(acc[2*q + 0], xv2, w.x);
            ffma2(acc[2*q + 1], xv2, w.y);
        }
    }
    float o[16];
    #pragma unroll
    for (int q = 0; q < 8; q++) {
        float2 v = unpack2(acc[q]);
        o[2*q]     = sp(v.x);
        o[2*q + 1] = sp(v.y);
    }

    __syncthreads();
    #pragma unroll
    for (int c = 0; c < 16; c++) Xs[ro + co3 + c] = o[c];
    __syncthreads();

    if (t < 32) {
        float s = 0.0f;
        for (int r = 0; r < 128; r++) s += Xs[r * 65 + t];
        atomicAdd(&g_atom_sum[b * NF + t], s);
    }
    {
        float* op = out + O_ATOMS + ((size_t)b * NAA + row0) * NF;
        for (int e = t; e < 128 * NF; e += 256)
            op[e] = Xs[(e >> 5) * 65 + (e & 31)];
    }
}

// ---------------- state MLP --------------------------------------------------
__global__ void __launch_bounds__(256)
k_state(const float* __restrict__ state,
        const float* __restrict__ w1, const float* __restrict__ b1,
        const float* __restrict__ w2, const float* __restrict__ b2,
        const float* __restrict__ w3, const float* __restrict__ b3,
        float* __restrict__ out)
{
    __shared__ float uin[BB][96];
    __shared__ float hh[BB][64];
    const int t = threadIdx.x;

    if (t < BB * 32) {
        int b = t >> 5, i = t & 31;
        uin[b][i]      = g_bond_sum[b * 32 + i] * (1.0f / NBB);
        uin[b][32 + i] = g_atom_sum[b * 32 + i] * (1.0f / NAA);
        uin[b][64 + i] = state[b * 32 + i];
    }
    __syncthreads();

    const int b = t >> 6, j = t & 63;
    float s = b1[j];
    for (int i = 0; i < 96; i++) s += uin[b][i] * w1[i * 64 + j];
    hh[b][j] = sp(s);
    __syncthreads();

    s = b2[j];
    for (int i = 0; i < 64; i++) s += hh[b][i] * w2[i * 64 + j];
    float h2v = sp(s);
    __syncthreads();
    hh[b][j] = h2v;
    __syncthreads();

    if (j < 32) {
        s = b3[j];
        for (int i = 0; i < 64; i++) s += hh[b][i] * w3[i * 32 + j];
        out[O_STATE + b * 32 + j] = sp(s);
    }
}

// ---------------- launch -----------------------------------------------------
extern "C" void kernel_launch(void* const* d_in, const int* in_sizes, int n_in,
                              void* d_out, int out_size)
{
    const float* bonds  = (const float*)d_in[0];
    const int*   ba1    = (const int*)  d_in[1];
    const int*   ba2    = (const int*)  d_in[2];
    const float* atoms  = (const float*)d_in[3];
    const float* state  = (const float*)d_in[4];
    const float* e_w1 = (const float*)d_in[5],  *e_b1 = (const float*)d_in[6];
    const float* e_w2 = (const float*)d_in[7],  *e_b2 = (const float*)d_in[8];
    const float* e_w3 = (const float*)d_in[9],  *e_b3 = (const float*)d_in[10];
    const float* v_w1 = (const float*)d_in[11], *v_b1 = (const float*)d_in[12];
    const float* v_w2 = (const float*)d_in[13], *v_b2 = (const float*)d_in[14];
    const float* v_w3 = (const float*)d_in[15], *v_b3 = (const float*)d_in[16];
    const float* u_w1 = (const float*)d_in[17], *u_b1 = (const float*)d_in[18];
    const float* u_w2 = (const float*)d_in[19], *u_b2 = (const float*)d_in[20];
    const float* u_w3 = (const float*)d_in[21], *u_b3 = (const float*)d_in[22];
    float* out = (float*)d_out;

    const int SMEM_BONDS = 25120 * 4;  // 100480 B
    const int SMEM_ATOMS = 18848 * 4;  //  75392 B
    cudaFuncSetAttribute(k_bonds, cudaFuncAttributeMaxDynamicSharedMemorySize, SMEM_BONDS);
    cudaFuncSetAttribute(k_atoms, cudaFuncAttributeMaxDynamicSharedMemorySize, SMEM_ATOMS);

    k_zero<<<512, 256>>>();
    k_bonds<<<BB * (NBB / 128), 256, SMEM_BONDS>>>(
        bonds, ba1, ba2, atoms, state,
        e_w1, e_b1, e_w2, e_b2, e_w3, e_b3, out);
    k_atoms<<<BB * (NAA / 128), 256, SMEM_ATOMS>>>(
        atoms, state,
        v_w1, v_b1, v_w2, v_b2, v_w3, v_b3, out);
    k_state<<<1, 256>>>(state, u_w1, u_b1, u_w2, u_b2, u_w3, u_b3, out);
}